// round 1
// baseline (speedup 1.0000x reference)
#include <cuda_runtime.h>
#include <cstdint>

#define NMAX 100000
#define EMAX 1600000
#define CDIV(a,b) (((a)+(b)-1)/(b))

// ---------------- scratch (static device globals; no runtime alloc) ----------------
__device__ float g_bufA[NMAX*128];   // node features (layer input / agg output)
__device__ float g_bufB[NMAX*128];   // GEMM output (pre-aggregation)
__device__ int   g_cnt[NMAX];
__device__ int   g_rowptr[NMAX+1];
__device__ int   g_cols[EMAX];
__device__ float g_vals[EMAX];
__device__ float g_dis[NMAX];        // rsqrt(deg)
__device__ float g_invdeg[NMAX];     // 1/deg  (self-loop norm)
__device__ float g_stats[256];       // [0:128) sum, [128:256) sumsq
__device__ float g_scale[128];
__device__ float g_shift[128];
__device__ int   g_is64;

// ---------------- edge index access (int64 vs int32, detected on device) -----------
__device__ __forceinline__ long long edge_at(const void* ei, long long idx, int is64){
    return is64 ? ((const long long*)ei)[idx] : (long long)((const int*)ei)[idx];
}

__global__ void k_detect(const void* ei){
    if (blockIdx.x==0 && threadIdx.x==0){
        const int* p = (const int*)ei;
        int all0 = 1;
        for (int k=0;k<128;k++) if (p[2*k+1]!=0){ all0=0; break; }
        g_is64 = all0;   // node ids < 2^31 -> high words all zero iff int64
    }
}

// ---------------- degree / CSR build ----------------
__global__ void k_zero_cnt(int n){
    int i = blockIdx.x*blockDim.x + threadIdx.x;
    if (i < n) g_cnt[i] = 0;
}

__global__ void k_hist(const void* ei, int E){
    int e = blockIdx.x*blockDim.x + threadIdx.x;
    if (e >= E) return;
    int is64 = g_is64;
    int d = (int)edge_at(ei, (long long)E + e, is64);
    atomicAdd(&g_cnt[d], 1);
}

__global__ void k_deg(int n){
    int i = blockIdx.x*blockDim.x + threadIdx.x;
    if (i >= n) return;
    float c = (float)(g_cnt[i] + 1);     // +1 self loop
    g_dis[i]    = rsqrtf(c);
    g_invdeg[i] = 1.0f / c;
}

// single-block exclusive scan of g_cnt -> g_rowptr (n up to 100k)
__global__ void k_scan(int n){
    __shared__ int sums[1024];
    int tid = threadIdx.x;
    int chunk = (n + 1023) / 1024;
    int start = tid * chunk;
    int end   = min(start + chunk, n);
    int s = 0;
    for (int i = start; i < end; i++) s += g_cnt[i];
    sums[tid] = s;
    __syncthreads();
    for (int off = 1; off < 1024; off <<= 1){
        int v = (tid >= off) ? sums[tid - off] : 0;
        __syncthreads();
        sums[tid] += v;
        __syncthreads();
    }
    int excl = (tid == 0) ? 0 : sums[tid-1];
    int off = excl;
    for (int i = start; i < end; i++){ g_rowptr[i] = off; off += g_cnt[i]; }
    if (tid == 1023) g_rowptr[n] = sums[1023];
}

__global__ void k_fill(const void* ei, int E){
    int e = blockIdx.x*blockDim.x + threadIdx.x;
    if (e >= E) return;
    int is64 = g_is64;
    int s = (int)edge_at(ei, e, is64);
    int d = (int)edge_at(ei, (long long)E + e, is64);
    int pos = g_rowptr[d] + atomicAdd(&g_cnt[d], 1);
    g_cols[pos] = s;
    g_vals[pos] = g_dis[s] * g_dis[d];
}

// ---------------- GEMM: C(n x DOUT) = A(n x 128) @ W(128 x DOUT), fp32 ----------------
// BM=64, BK=16 tiles, 256 threads, per-thread 8 x (DOUT/32) outputs.
template<int DOUT, int ASEL>
__global__ void __launch_bounds__(256) k_gemm(const float* __restrict__ Aext,
                                              const float* __restrict__ W, int n){
    constexpr int BM = 64, BK = 16;
    constexpr int TN = DOUT / 32;               // 4 (DOUT=128) or 2 (DOUT=64)
    const float* A = (ASEL == 0) ? Aext : g_bufA;
    float* C = g_bufB;

    __shared__ __align__(16) float Xs[BK][BM + 1];
    __shared__ __align__(16) float Ws[BK][DOUT];

    int tid  = threadIdx.x;
    int tcol = tid & 31;
    int trow = tid >> 5;                        // 0..7
    int rowBase = blockIdx.x * BM;

    float acc[8][TN];
    #pragma unroll
    for (int i=0;i<8;i++)
        #pragma unroll
        for (int j=0;j<TN;j++) acc[i][j] = 0.f;

    int xr  = tid >> 2;    // 0..63 (row within tile)
    int xk4 = tid & 3;     // 0..3  (float4 along K)

    for (int kt = 0; kt < 128; kt += BK){
        // load X tile (transposed into Xs[k][m])
        float4 xv = make_float4(0.f,0.f,0.f,0.f);
        int grow = rowBase + xr;
        if (grow < n) xv = *(const float4*)&A[(long long)grow*128 + kt + xk4*4];
        Xs[xk4*4+0][xr] = xv.x;
        Xs[xk4*4+1][xr] = xv.y;
        Xs[xk4*4+2][xr] = xv.z;
        Xs[xk4*4+3][xr] = xv.w;
        // load W tile
        constexpr int NF4 = BK*DOUT/4;          // float4 count (512 or 256)
        #pragma unroll
        for (int t = 0; t < NF4/256; t++){
            int idx = tid + t*256;
            int wr  = idx / (DOUT/4);
            int wc4 = idx % (DOUT/4);
            *(float4*)&Ws[wr][wc4*4] = *(const float4*)&W[(long long)(kt+wr)*DOUT + wc4*4];
        }
        __syncthreads();

        #pragma unroll
        for (int k = 0; k < BK; k++){
            float xv_[8];
            #pragma unroll
            for (int i=0;i<8;i++) xv_[i] = Xs[k][trow*8 + i];
            float wv_[TN];
            if constexpr (TN == 4){
                float4 w4 = *(const float4*)&Ws[k][tcol*4];
                wv_[0]=w4.x; wv_[1]=w4.y; wv_[2]=w4.z; wv_[3]=w4.w;
            } else {
                float2 w2 = *(const float2*)&Ws[k][tcol*2];
                wv_[0]=w2.x; wv_[1]=w2.y;
            }
            #pragma unroll
            for (int i=0;i<8;i++)
                #pragma unroll
                for (int j=0;j<TN;j++) acc[i][j] += xv_[i]*wv_[j];
        }
        __syncthreads();
    }

    #pragma unroll
    for (int i=0;i<8;i++){
        int r = rowBase + trow*8 + i;
        if (r < n){
            if constexpr (TN == 4){
                float4 v = make_float4(acc[i][0],acc[i][1],acc[i][2],acc[i][3]);
                *(float4*)&C[(long long)r*DOUT + tcol*4] = v;
            } else {
                float2 v = make_float2(acc[i][0],acc[i][1]);
                *(float2*)&C[(long long)r*DOUT + tcol*2] = v;
            }
        }
    }
}

// ---------------- aggregation: bufA = self + sum_{edges dst=i} norm * bufB[src] ------
template<int D>
__global__ void k_agg(int n){
    constexpr int F   = D/4;        // float4 per row (32 or 16)
    constexpr int NPW = 32/F;       // nodes per warp (1 or 2)
    int tid  = blockIdx.x*blockDim.x + threadIdx.x;
    int lane = threadIdx.x & 31;
    int warp = tid >> 5;
    int node = warp*NPW + lane/F;
    int fi   = lane % F;
    if (node >= n) return;

    const float4* t = (const float4*)g_bufB;
    float4* o = (float4*)g_bufA;

    float idg = g_invdeg[node];
    float4 v = t[(long long)node*F + fi];
    float4 acc = make_float4(v.x*idg, v.y*idg, v.z*idg, v.w*idg);

    int p0 = g_rowptr[node], p1 = g_rowptr[node+1];
    for (int p = p0; p < p1; p++){
        int   s = g_cols[p];
        float w = g_vals[p];
        float4 u = t[(long long)s*F + fi];
        acc.x += w*u.x; acc.y += w*u.y; acc.z += w*u.z; acc.w += w*u.w;
    }
    o[(long long)node*F + fi] = acc;
}

// ---------------- batch norm ----------------
__global__ void k_zero_stats(){
    g_stats[threadIdx.x] = 0.f;   // launched with 256 threads
}

template<int D>
__global__ void k_bn_stats(int n){
    int tid = threadIdx.x;                       // blockDim = 256 (multiple of D)
    long long total  = (long long)n * D;
    long long stride = (long long)gridDim.x * blockDim.x;   // multiple of D
    float s = 0.f, q = 0.f;
    for (long long i = (long long)blockIdx.x*blockDim.x + tid; i < total; i += stride){
        float v = g_bufA[i];
        s += v; q += v*v;
    }
    __shared__ float ss[256], sq[256];
    ss[tid] = s; sq[tid] = q;
    __syncthreads();
    for (int off = 128; off >= D; off >>= 1){
        if (tid < off){ ss[tid] += ss[tid+off]; sq[tid] += sq[tid+off]; }
        __syncthreads();
    }
    if (tid < D){
        atomicAdd(&g_stats[tid],       ss[tid]);
        atomicAdd(&g_stats[128 + tid], sq[tid]);
    }
}

__global__ void k_bn_final(const float* __restrict__ g, const float* __restrict__ be,
                           int n, int D){
    int c = threadIdx.x;
    if (c < D){
        float inv_n = 1.0f / (float)n;
        float mu  = g_stats[c] * inv_n;
        float var = g_stats[128 + c] * inv_n - mu*mu;
        float sc  = g[c] * rsqrtf(var + 1e-5f);
        g_scale[c] = sc;
        g_shift[c] = be[c] - mu*sc;
    }
}

template<int D>
__global__ void k_bn_apply(int n){
    int total = n * (D/4);
    int idx = blockIdx.x*blockDim.x + threadIdx.x;
    if (idx >= total) return;
    int c4 = idx % (D/4);
    float4 v  = ((const float4*)g_bufA)[idx];
    float4 sc = ((const float4*)g_scale)[c4];
    float4 sh = ((const float4*)g_shift)[c4];
    v.x = fmaxf(fmaf(v.x, sc.x, sh.x), 0.f);
    v.y = fmaxf(fmaf(v.y, sc.y, sh.y), 0.f);
    v.z = fmaxf(fmaf(v.z, sc.z, sh.z), 0.f);
    v.w = fmaxf(fmaf(v.w, sc.w, sh.w), 0.f);
    ((float4*)g_bufA)[idx] = v;
}

// ---------------- head: out = relu(h @ wc1 + bc1) @ wc2 + bc2, h = bufA (n x 64) -----
__global__ void __launch_bounds__(256) k_head(const float* __restrict__ wc1,
                                              const float* __restrict__ bc1,
                                              const float* __restrict__ wc2,
                                              const float* __restrict__ bc2,
                                              float* __restrict__ out, int n){
    __shared__ float w1s[64*32];
    __shared__ float b1s[32], w2s[32];
    int tid = threadIdx.x;
    for (int i = tid; i < 64*32; i += 256) w1s[i] = wc1[i];
    if (tid < 32){ b1s[tid] = bc1[tid]; w2s[tid] = wc2[tid]; }
    __syncthreads();

    int warp = (blockIdx.x*256 + tid) >> 5;
    int lane = tid & 31;
    if (warp >= n) return;

    const float* row = &g_bufA[(long long)warp * 64];
    float a0 = b1s[lane], a1 = 0.f, a2 = 0.f, a3 = 0.f;
    #pragma unroll
    for (int k = 0; k < 64; k += 4){
        a0 += row[k+0] * w1s[(k+0)*32 + lane];
        a1 += row[k+1] * w1s[(k+1)*32 + lane];
        a2 += row[k+2] * w1s[(k+2)*32 + lane];
        a3 += row[k+3] * w1s[(k+3)*32 + lane];
    }
    float h = fmaxf((a0+a1)+(a2+a3), 0.f) * w2s[lane];
    #pragma unroll
    for (int off = 16; off; off >>= 1) h += __shfl_xor_sync(0xffffffff, h, off);
    if (lane == 0) out[warp] = h + bc2[0];
}

// ---------------- launch ----------------
extern "C" void kernel_launch(void* const* d_in, const int* in_sizes, int n_in,
                              void* d_out, int out_size){
    const float* x   = (const float*)d_in[0];
    const void*  ei  = d_in[1];
    const float* w0  = (const float*)d_in[2];
    const float* g0  = (const float*)d_in[4];
    const float* be0 = (const float*)d_in[5];
    const float* w1  = (const float*)d_in[6];
    const float* g1  = (const float*)d_in[8];
    const float* be1 = (const float*)d_in[9];
    const float* w2  = (const float*)d_in[10];
    const float* g2  = (const float*)d_in[12];
    const float* be2 = (const float*)d_in[13];
    const float* wc1 = (const float*)d_in[14];
    const float* bc1 = (const float*)d_in[15];
    const float* wc2 = (const float*)d_in[16];
    const float* bc2 = (const float*)d_in[17];
    float* out = (float*)d_out;

    int n = in_sizes[0] / 128;
    int E = in_sizes[1] / 2;

    // CSR + normalization build (once per call)
    k_detect<<<1,1>>>(ei);
    k_zero_cnt<<<CDIV(n,256),256>>>(n);
    k_hist<<<CDIV(E,256),256>>>(ei, E);
    k_deg<<<CDIV(n,256),256>>>(n);
    k_scan<<<1,1024>>>(n);
    k_zero_cnt<<<CDIV(n,256),256>>>(n);
    k_fill<<<CDIV(E,256),256>>>(ei, E);

    // ---- layer 0 (128 -> 128) ----
    k_gemm<128,0><<<CDIV(n,64),256>>>(x, w0, n);
    k_agg<128><<<CDIV(n*32,256),256>>>(n);
    k_zero_stats<<<1,256>>>();
    k_bn_stats<128><<<1024,256>>>(n);
    k_bn_final<<<1,128>>>(g0, be0, n, 128);
    k_bn_apply<128><<<CDIV(n*32,256),256>>>(n);

    // ---- layer 1 (128 -> 128) ----
    k_gemm<128,1><<<CDIV(n,64),256>>>(x, w1, n);
    k_agg<128><<<CDIV(n*32,256),256>>>(n);
    k_zero_stats<<<1,256>>>();
    k_bn_stats<128><<<1024,256>>>(n);
    k_bn_final<<<1,128>>>(g1, be1, n, 128);
    k_bn_apply<128><<<CDIV(n*32,256),256>>>(n);

    // ---- layer 2 (128 -> 64) ----
    k_gemm<64,1><<<CDIV(n,64),256>>>(x, w2, n);
    k_agg<64><<<CDIV(n*16,256),256>>>(n);
    k_zero_stats<<<1,256>>>();
    k_bn_stats<64><<<1024,256>>>(n);
    k_bn_final<<<1,64>>>(g2, be2, n, 64);
    k_bn_apply<64><<<CDIV(n*16,256),256>>>(n);

    // ---- head ----
    k_head<<<CDIV(n*32,256),256>>>(wc1, bc1, wc2, bc2, out, n);
}